// round 11
// baseline (speedup 1.0000x reference)
#include <cuda_runtime.h>
#include <cuda_bf16.h>
#include <cstdint>

#define N_NODES 50000
#define N_EDGES 800000
#define F_IN    64
#define F_MID   128
#define GTILE   128
#define NTILES  ((N_NODES + GTILE - 1) / GTILE)   // 391

typedef unsigned long long u64;

// ---------------- scratch (device globals; no allocations) ----------------
__device__ int   g_deg_out[N_NODES];
__device__ int   g_deg_in [N_NODES];
__device__ float g_norm_src[N_NODES];
__device__ float g_norm_dst[N_NODES];
__device__ int   g_off [N_NODES];
__device__ int   g_alloc;
__device__ int   g_rank[N_EDGES];
__device__ int   g_esrc[N_EDGES];
__device__ float g_hs  [(size_t)N_NODES * F_IN];
__device__ float g_agg1[(size_t)N_NODES * F_IN];
__device__ float g_t2  [(size_t)N_NODES * F_IN];

// Dynamic smem layout for fused GEMM (float offsets).
// BUF region is aliased: As2 (dup A, 128x128 fl) during phase1 k-loop,
// H1s2 (dup h1, 128x260 fl) from phase1 epilogue onward.
#define WS1_OFF 0                    // 8192 floats
#define WS2_OFF 8192                 // 8192 floats
#define BUF_OFF 16384
#define H1S2_STRIDE 260              // 256 dup cols + pad
#define SMEM_FLOATS (BUF_OFF + GTILE * H1S2_STRIDE)   // 49664
#define SMEM_BYTES  (SMEM_FLOATS * 4)                 // 198656

// ---------------- f32x2 helpers (bit-exact vs scalar fp32) ----------------
__device__ __forceinline__ void fma2(u64& d, u64 a, u64 b) {
    asm("fma.rn.f32x2 %0, %1, %2, %0;" : "+l"(d) : "l"(a), "l"(b));
}
__device__ __forceinline__ void add2(u64& d, u64 v) {
    asm("add.rn.f32x2 %0, %0, %1;" : "+l"(d) : "l"(v));
}
__device__ __forceinline__ float2 unpack2(u64 v) {
    float2 r; asm("mov.b64 {%0,%1}, %2;" : "=f"(r.x), "=f"(r.y) : "l"(v)); return r;
}

// ---------------- kernels ----------------

__global__ void zero_kernel() {
    int i = blockIdx.x * blockDim.x + threadIdx.x;
    if (i < N_NODES) { g_deg_out[i] = 0; g_deg_in[i] = 0; }
    if (i == 0) g_alloc = 0;
}

__global__ void degree_kernel(const int* __restrict__ src,
                              const int* __restrict__ dst) {
    int t = blockIdx.x * blockDim.x + threadIdx.x;
    if (t >= N_EDGES / 2) return;
    int2 s = __ldg(reinterpret_cast<const int2*>(src) + t);
    int2 d = __ldg(reinterpret_cast<const int2*>(dst) + t);
    atomicAdd(&g_deg_out[s.x], 1);
    atomicAdd(&g_deg_out[s.y], 1);
    int2 r;
    r.x = atomicAdd(&g_deg_in[d.x], 1);
    r.y = atomicAdd(&g_deg_in[d.y], 1);
    reinterpret_cast<int2*>(g_rank)[t] = r;
}

// Per-block smem scan + one atomic per block for CSR offsets; norms.
__global__ __launch_bounds__(256) void norm_offset_kernel() {
    __shared__ int s[256];
    __shared__ int base;
    int t = threadIdx.x;
    int i = blockIdx.x * 256 + t;
    int deg = 0, dout = 0;
    if (i < N_NODES) { deg = g_deg_in[i]; dout = g_deg_out[i]; }
    s[t] = deg;
    __syncthreads();
#pragma unroll
    for (int o = 1; o < 256; o <<= 1) {
        int v = (t >= o) ? s[t - o] : 0;
        __syncthreads();
        s[t] += v;
        __syncthreads();
    }
    if (t == 255) base = atomicAdd(&g_alloc, s[255]);
    __syncthreads();
    if (i < N_NODES) {
        g_off[i] = base + s[t] - deg;
        g_norm_src[i] = rsqrtf(fmaxf((float)dout, 1.f));
        g_norm_dst[i] = rsqrtf(fmaxf((float)deg,  1.f));
    }
}

// Merged: CSR fill (latency-bound scatter) co-runs with prescale (BW-bound).
#define FILL_BLOCKS ((N_EDGES / 2 + 255) / 256)         // 1563
#define PRE_BLOCKS  ((N_NODES * F_IN / 4 + 255) / 256)  // 3125
__global__ void fill_prescale_kernel(const int* __restrict__ src,
                                     const int* __restrict__ dst,
                                     const float* __restrict__ h) {
    int b = blockIdx.x;
    if (b < FILL_BLOCKS) {
        int t = b * blockDim.x + threadIdx.x;
        if (t >= N_EDGES / 2) return;
        int2 s = __ldg(reinterpret_cast<const int2*>(src) + t);
        int2 d = __ldg(reinterpret_cast<const int2*>(dst) + t);
        int2 r = *(reinterpret_cast<const int2*>(g_rank) + t);
        int px = __ldg(&g_off[d.x]) + r.x;
        int py = __ldg(&g_off[d.y]) + r.y;
        g_esrc[px] = s.x;
        g_esrc[py] = s.y;
    } else {
        int i = (b - FILL_BLOCKS) * blockDim.x + threadIdx.x;
        const int NF4 = N_NODES * F_IN / 4;
        if (i >= NF4) return;
        float ns = __ldg(&g_norm_src[i >> 4]);
        float4 v = __ldg(reinterpret_cast<const float4*>(h) + i);
        v.x *= ns; v.y *= ns; v.z *= ns; v.w *= ns;
        reinterpret_cast<float4*>(g_hs)[i] = v;
    }
}

// Accumulate one source row chunk (2x16B) into 4 packed-f32x2 accumulators.
__device__ __forceinline__ void acc_row2(const float* __restrict__ base, int s, int c8,
                                         u64* a) {
    const ulonglong2* p = reinterpret_cast<const ulonglong2*>(base + (size_t)s * F_IN + c8);
    ulonglong2 v0 = __ldg(p);
    ulonglong2 v1 = __ldg(p + 1);
    add2(a[0], v0.x); add2(a[1], v0.y);
    add2(a[2], v1.x); add2(a[3], v1.y);
}

// Pull-aggregation layer 1 (f32x2 adds).
__global__ void aggregate1_kernel() {
    int tid = blockIdx.x * blockDim.x + threadIdx.x;
    int n = tid >> 3;
    if (n >= N_NODES) return;
    int c8 = (tid & 7) << 3;
    int i   = __ldg(&g_off[n]);
    int end = i + __ldg(&g_deg_in[n]);
    u64 a[4] = {0ull, 0ull, 0ull, 0ull};
    while ((i & 3) && i < end) acc_row2(g_hs, __ldg(&g_esrc[i++]), c8, a);
    const int4* e4 = reinterpret_cast<const int4*>(g_esrc);
    for (; i + 4 <= end; i += 4) {
        int4 q = __ldg(&e4[i >> 2]);
        acc_row2(g_hs, q.x, c8, a);
        acc_row2(g_hs, q.y, c8, a);
        acc_row2(g_hs, q.z, c8, a);
        acc_row2(g_hs, q.w, c8, a);
    }
    for (; i < end; i++) acc_row2(g_hs, __ldg(&g_esrc[i]), c8, a);
    ulonglong2* o = reinterpret_cast<ulonglong2*>(g_agg1 + (size_t)n * F_IN + c8);
    ulonglong2 s0; s0.x = a[0]; s0.y = a[1];
    ulonglong2 s1; s1.x = a[2]; s1.y = a[3];
    o[0] = s0; o[1] = s1;
}

// Fused persistent GEMM, FFMA2 throughout. 1024 threads, grid=148.
// phase1: h1 = relu(nd*(agg1@W1)+b1) -> H1s2 (column-duplicated, aliased over As2)
// phase2: t2 = ns*(h1@W2) -> gmem
__global__ __launch_bounds__(1024) void fused_gemm_kernel(const float* __restrict__ W1,
                                                          const float* __restrict__ b1,
                                                          const float* __restrict__ W2) {
    extern __shared__ __align__(16) float sm[];
    float* Ws1  = sm + WS1_OFF;   // [k][128 cols]
    float* Ws2  = sm + WS2_OFF;   // [k][64 cols]
    float* As2  = sm + BUF_OFF;   // [row][128] = 64 k values duplicated
    float* H1s2 = sm + BUF_OFF;   // [row][260] = 128 cols duplicated (aliased)
    int t = threadIdx.x;

    for (int i = t; i < F_IN * F_MID / 4; i += 1024)
        reinterpret_cast<float4*>(Ws1)[i] = __ldg(reinterpret_cast<const float4*>(W1) + i);
    for (int i = t; i < F_MID * F_IN / 4; i += 1024)
        reinterpret_cast<float4*>(Ws2)[i] = __ldg(reinterpret_cast<const float4*>(W2) + i);

    // phase1 mapping: rows {2rg, 2rg+1}, cols 8cg..8cg+7
    int cg = t & 15;
    int rg = t >> 4;           // 0..63
    // phase2 mapping: rows {2rg2, 2rg2+1}, cols 4cg2..4cg2+3
    int cg2 = t & 15;
    int rg2 = t >> 4;          // 0..63

    float4 bbA = __ldg(reinterpret_cast<const float4*>(b1) + (cg << 1));
    float4 bbB = __ldg(reinterpret_cast<const float4*>(b1) + (cg << 1) + 1);

    for (int tile = blockIdx.x; tile < NTILES; tile += gridDim.x) {
        int row0 = tile * GTILE;
        __syncthreads();   // previous tile's phase2 reads complete

        // Fill As2: duplicated A values, row-major [row][2k],[2k+1]
        for (int i = t; i < GTILE * F_IN / 4; i += 1024) {   // 2048
            int r  = i >> 4;
            int c4 = i & 15;            // k-chunk of 4
            int row = row0 + r;
            float4 v = (row < N_NODES)
                ? __ldg(reinterpret_cast<const float4*>(g_agg1 + (size_t)row * F_IN) + c4)
                : make_float4(0.f, 0.f, 0.f, 0.f);
            float2* dstp = reinterpret_cast<float2*>(&As2[r * 128 + (c4 << 3)]);
            dstp[0] = make_float2(v.x, v.x);
            dstp[1] = make_float2(v.y, v.y);
            dstp[2] = make_float2(v.z, v.z);
            dstp[3] = make_float2(v.w, v.w);
        }
        __syncthreads();

        // ---- phase 1 k-loop: FFMA2, 2 rows x 4 col-pairs ----
        u64 acc[2][4];
#pragma unroll
        for (int r = 0; r < 2; r++)
#pragma unroll
            for (int c = 0; c < 4; c++) acc[r][c] = 0ull;

        int r0 = rg << 1, r1 = r0 + 1;
#pragma unroll 8
        for (int k2 = 0; k2 < F_IN / 2; k2++) {
            ulonglong2 aA = *reinterpret_cast<const ulonglong2*>(&As2[r0 * 128 + (k2 << 2)]);
            ulonglong2 aB = *reinterpret_cast<const ulonglong2*>(&As2[r1 * 128 + (k2 << 2)]);
            int k = k2 << 1;
            ulonglong2 w0 = *reinterpret_cast<const ulonglong2*>(&Ws1[k * F_MID + (cg << 3)]);
            ulonglong2 w1 = *reinterpret_cast<const ulonglong2*>(&Ws1[k * F_MID + (cg << 3) + 4]);
            ulonglong2 w2 = *reinterpret_cast<const ulonglong2*>(&Ws1[(k + 1) * F_MID + (cg << 3)]);
            ulonglong2 w3 = *reinterpret_cast<const ulonglong2*>(&Ws1[(k + 1) * F_MID + (cg << 3) + 4]);
            fma2(acc[0][0], aA.x, w0.x); fma2(acc[0][1], aA.x, w0.y);
            fma2(acc[0][2], aA.x, w1.x); fma2(acc[0][3], aA.x, w1.y);
            fma2(acc[1][0], aB.x, w0.x); fma2(acc[1][1], aB.x, w0.y);
            fma2(acc[1][2], aB.x, w1.x); fma2(acc[1][3], aB.x, w1.y);
            fma2(acc[0][0], aA.y, w2.x); fma2(acc[0][1], aA.y, w2.y);
            fma2(acc[0][2], aA.y, w3.x); fma2(acc[0][3], aA.y, w3.y);
            fma2(acc[1][0], aB.y, w2.x); fma2(acc[1][1], aB.y, w2.y);
            fma2(acc[1][2], aB.y, w3.x); fma2(acc[1][3], aB.y, w3.y);
        }
        __syncthreads();   // all As2 reads done; BUF may be rewritten as H1s2

        // phase1 epilogue: relu(fma) and write DUPLICATED h1 into H1s2
#pragma unroll
        for (int r = 0; r < 2; r++) {
            int lr = r0 + r;
            int row = row0 + lr;
            float nd = (row < N_NODES) ? __ldg(&g_norm_dst[row]) : 0.f;
            float2 u0 = unpack2(acc[r][0]);
            float2 u1 = unpack2(acc[r][1]);
            float2 u2 = unpack2(acc[r][2]);
            float2 u3 = unpack2(acc[r][3]);
            float o0 = fmaxf(fmaf(u0.x, nd, bbA.x), 0.f);
            float o1 = fmaxf(fmaf(u0.y, nd, bbA.y), 0.f);
            float o2 = fmaxf(fmaf(u1.x, nd, bbA.z), 0.f);
            float o3 = fmaxf(fmaf(u1.y, nd, bbA.w), 0.f);
            float o4 = fmaxf(fmaf(u2.x, nd, bbB.x), 0.f);
            float o5 = fmaxf(fmaf(u2.y, nd, bbB.y), 0.f);
            float o6 = fmaxf(fmaf(u3.x, nd, bbB.z), 0.f);
            float o7 = fmaxf(fmaf(u3.y, nd, bbB.w), 0.f);
            float4* dst = reinterpret_cast<float4*>(&H1s2[lr * H1S2_STRIDE + (cg << 4)]);
            dst[0] = make_float4(o0, o0, o1, o1);
            dst[1] = make_float4(o2, o2, o3, o3);
            dst[2] = make_float4(o4, o4, o5, o5);
            dst[3] = make_float4(o6, o6, o7, o7);
        }
        __syncthreads();

        // ---- phase 2 k-loop: FFMA2, 2 rows x 2 col-pairs ----
        u64 acc2[2][2];
        acc2[0][0] = acc2[0][1] = acc2[1][0] = acc2[1][1] = 0ull;
        int p0 = rg2 << 1, p1 = p0 + 1;
#pragma unroll 8
        for (int k2 = 0; k2 < F_MID / 2; k2++) {
            ulonglong2 aA = *reinterpret_cast<const ulonglong2*>(&H1s2[p0 * H1S2_STRIDE + (k2 << 2)]);
            ulonglong2 aB = *reinterpret_cast<const ulonglong2*>(&H1s2[p1 * H1S2_STRIDE + (k2 << 2)]);
            int k = k2 << 1;
            ulonglong2 w0 = *reinterpret_cast<const ulonglong2*>(&Ws2[k * F_IN + (cg2 << 2)]);
            ulonglong2 w1 = *reinterpret_cast<const ulonglong2*>(&Ws2[(k + 1) * F_IN + (cg2 << 2)]);
            fma2(acc2[0][0], aA.x, w0.x); fma2(acc2[0][1], aA.x, w0.y);
            fma2(acc2[1][0], aB.x, w0.x); fma2(acc2[1][1], aB.x, w0.y);
            fma2(acc2[0][0], aA.y, w1.x); fma2(acc2[0][1], aA.y, w1.y);
            fma2(acc2[1][0], aB.y, w1.x); fma2(acc2[1][1], aB.y, w1.y);
        }
#pragma unroll
        for (int r = 0; r < 2; r++) {
            int row = row0 + p0 + r;
            if (row < N_NODES) {
                float ns = __ldg(&g_norm_src[row]);
                float2 u0 = unpack2(acc2[r][0]);
                float2 u1 = unpack2(acc2[r][1]);
                float4 o;
                o.x = u0.x * ns; o.y = u0.y * ns;
                o.z = u1.x * ns; o.w = u1.y * ns;
                *reinterpret_cast<float4*>(g_t2 + (size_t)row * F_IN + (cg2 << 2)) = o;
            }
        }
    }
}

// Pull-aggregation layer 2 + fused epilogue (f32x2 adds).
__global__ void aggregate2_kernel(const float* __restrict__ b2,
                                  float* __restrict__ out) {
    int tid = blockIdx.x * blockDim.x + threadIdx.x;
    int n = tid >> 3;
    if (n >= N_NODES) return;
    int c8 = (tid & 7) << 3;
    int i   = __ldg(&g_off[n]);
    int end = i + __ldg(&g_deg_in[n]);
    u64 a[4] = {0ull, 0ull, 0ull, 0ull};
    while ((i & 3) && i < end) acc_row2(g_t2, __ldg(&g_esrc[i++]), c8, a);
    const int4* e4 = reinterpret_cast<const int4*>(g_esrc);
    for (; i + 4 <= end; i += 4) {
        int4 q = __ldg(&e4[i >> 2]);
        acc_row2(g_t2, q.x, c8, a);
        acc_row2(g_t2, q.y, c8, a);
        acc_row2(g_t2, q.z, c8, a);
        acc_row2(g_t2, q.w, c8, a);
    }
    for (; i < end; i++) acc_row2(g_t2, __ldg(&g_esrc[i]), c8, a);

    float nd = __ldg(&g_norm_dst[n]);
    float4 b0 = __ldg(reinterpret_cast<const float4*>(b2) + (c8 >> 2));
    float4 b1v = __ldg(reinterpret_cast<const float4*>(b2) + (c8 >> 2) + 1);
    float2 f0 = unpack2(a[0]), f1 = unpack2(a[1]);
    float2 f2 = unpack2(a[2]), f3 = unpack2(a[3]);
    float4 o0, o1;
    o0.x = fmaf(f0.x, nd, b0.x);  o0.y = fmaf(f0.y, nd, b0.y);
    o0.z = fmaf(f1.x, nd, b0.z);  o0.w = fmaf(f1.y, nd, b0.w);
    o1.x = fmaf(f2.x, nd, b1v.x); o1.y = fmaf(f2.y, nd, b1v.y);
    o1.z = fmaf(f3.x, nd, b1v.z); o1.w = fmaf(f3.y, nd, b1v.w);
    float4* o = reinterpret_cast<float4*>(out + (size_t)n * F_IN + c8);
    o[0] = o0; o[1] = o1;
}

// ---------------- launch ----------------
extern "C" void kernel_launch(void* const* d_in, const int* in_sizes, int n_in,
                              void* d_out, int out_size) {
    const float* h   = (const float*)d_in[0];
    const int*   src = (const int*)  d_in[1];
    const int*   dst = (const int*)  d_in[2];
    const float* W1  = (const float*)d_in[3];
    const float* b1  = (const float*)d_in[4];
    const float* W2  = (const float*)d_in[5];
    const float* b2  = (const float*)d_in[6];
    float* out = (float*)d_out;

    cudaFuncSetAttribute(fused_gemm_kernel,
                         cudaFuncAttributeMaxDynamicSharedMemorySize, SMEM_BYTES);

    zero_kernel<<<(N_NODES + 255) / 256, 256>>>();
    degree_kernel<<<(N_EDGES / 2 + 255) / 256, 256>>>(src, dst);
    norm_offset_kernel<<<(N_NODES + 255) / 256, 256>>>();
    fill_prescale_kernel<<<FILL_BLOCKS + PRE_BLOCKS, 256>>>(src, dst, h);

    const int a_threads = N_NODES * 8;
    aggregate1_kernel<<<(a_threads + 255) / 256, 256>>>();

    fused_gemm_kernel<<<148, 1024, SMEM_BYTES>>>(W1, b1, W2);

    aggregate2_kernel<<<(a_threads + 255) / 256, 256>>>(b2, out);
}

// round 13
// speedup vs baseline: 1.3430x; 1.3430x over previous
#include <cuda_runtime.h>
#include <cuda_bf16.h>
#include <cstdint>

#define N_NODES 50000
#define N_EDGES 800000
#define F_IN    64
#define F_MID   128
#define GTILE   128          // rows per fused-GEMM tile
#define NTILES  ((N_NODES + GTILE - 1) / GTILE)   // 391

typedef unsigned long long u64;

// ---------------- scratch (device globals; no allocations) ----------------
__device__ int   g_deg_out[N_NODES];
__device__ int   g_deg_in [N_NODES];
__device__ float g_norm_src[N_NODES];
__device__ float g_norm_dst[N_NODES];
__device__ int   g_off [N_NODES];
__device__ int   g_alloc;
__device__ int   g_rank[N_EDGES];
__device__ int   g_esrc[N_EDGES];
__device__ float g_hs  [(size_t)N_NODES * F_IN];
__device__ float g_agg1[(size_t)N_NODES * F_IN];
__device__ float g_t2  [(size_t)N_NODES * F_IN];

// Dynamic smem layout for fused GEMM (float offsets) — identical to R10.
#define WS1_OFF 0                              // [64*128]          8192 floats
#define WS2_OFF 8192                           // [128*64]          8192 floats
#define AS_OFF  16384                          // [128 rows][64 k]  8192 floats
#define H1_OFF  24576                          // [128 rows][132]  16896 floats
#define SMEM_FLOATS (H1_OFF + GTILE * 132)     // 41472
#define SMEM_BYTES (SMEM_FLOATS * 4)           // 165888

// ---------------- f32x2 helpers (bit-exact vs scalar fp32) ----------------
__device__ __forceinline__ u64 pack_dup(float v) {
    u64 r; asm("mov.b64 %0, {%1,%1};" : "=l"(r) : "f"(v)); return r;
}
__device__ __forceinline__ void fma2(u64& d, u64 a, u64 b) {
    asm("fma.rn.f32x2 %0, %1, %2, %0;" : "+l"(d) : "l"(a), "l"(b));
}
__device__ __forceinline__ float2 unpack2(u64 v) {
    float2 r; asm("mov.b64 {%0,%1}, %2;" : "=f"(r.x), "=f"(r.y) : "l"(v)); return r;
}

// ---------------- kernels (identical to R10 except fused_gemm inner loops) --

__global__ void zero_kernel() {
    int i = blockIdx.x * blockDim.x + threadIdx.x;
    if (i < N_NODES) { g_deg_out[i] = 0; g_deg_in[i] = 0; }
    if (i == 0) g_alloc = 0;
}

__global__ void degree_kernel(const int* __restrict__ src,
                              const int* __restrict__ dst) {
    int t = blockIdx.x * blockDim.x + threadIdx.x;
    if (t >= N_EDGES / 2) return;
    int2 s = __ldg(reinterpret_cast<const int2*>(src) + t);
    int2 d = __ldg(reinterpret_cast<const int2*>(dst) + t);
    atomicAdd(&g_deg_out[s.x], 1);
    atomicAdd(&g_deg_out[s.y], 1);
    int2 r;
    r.x = atomicAdd(&g_deg_in[d.x], 1);
    r.y = atomicAdd(&g_deg_in[d.y], 1);
    reinterpret_cast<int2*>(g_rank)[t] = r;
}

// Scan for CSR offsets + norms + fused prescale of this block's 256 rows.
__global__ __launch_bounds__(256) void norm_offset_prescale_kernel(const float* __restrict__ h) {
    __shared__ int   s[256];
    __shared__ int   base;
    __shared__ float ns_s[256];
    int t = threadIdx.x;
    int i = blockIdx.x * 256 + t;
    int deg = 0, dout = 0;
    if (i < N_NODES) { deg = g_deg_in[i]; dout = g_deg_out[i]; }
    s[t] = deg;
    __syncthreads();
#pragma unroll
    for (int o = 1; o < 256; o <<= 1) {
        int v = (t >= o) ? s[t - o] : 0;
        __syncthreads();
        s[t] += v;
        __syncthreads();
    }
    if (t == 255) base = atomicAdd(&g_alloc, s[255]);
    float nsv = rsqrtf(fmaxf((float)dout, 1.f));
    ns_s[t] = nsv;
    __syncthreads();
    if (i < N_NODES) {
        g_off[i] = base + s[t] - deg;
        g_norm_src[i] = nsv;
        g_norm_dst[i] = rsqrtf(fmaxf((float)deg, 1.f));
    }
    int base_row = blockIdx.x * 256;
    const float4* h4 = reinterpret_cast<const float4*>(h);
    float4* hs4 = reinterpret_cast<float4*>(g_hs);
#pragma unroll
    for (int j = 0; j < 16; j++) {
        int idx = j * 256 + t;
        int lr = idx >> 4;
        int c4 = idx & 15;
        int row = base_row + lr;
        if (row < N_NODES) {
            float ns = ns_s[lr];
            float4 v = __ldg(&h4[(size_t)row * 16 + c4]);
            v.x *= ns; v.y *= ns; v.z *= ns; v.w *= ns;
            hs4[(size_t)row * 16 + c4] = v;
        }
    }
}

__global__ void fill_kernel(const int* __restrict__ src,
                            const int* __restrict__ dst) {
    int t = blockIdx.x * blockDim.x + threadIdx.x;
    if (t >= N_EDGES / 2) return;
    int2 s = __ldg(reinterpret_cast<const int2*>(src) + t);
    int2 d = __ldg(reinterpret_cast<const int2*>(dst) + t);
    int2 r = *(reinterpret_cast<const int2*>(g_rank) + t);
    int px = __ldg(&g_off[d.x]) + r.x;
    int py = __ldg(&g_off[d.y]) + r.y;
    g_esrc[px] = s.x;
    g_esrc[py] = s.y;
}

__device__ __forceinline__ void acc_row(const float4* __restrict__ base4, int s, int c2,
                                        float4& a0, float4& a1) {
    const float4* p = base4 + (size_t)s * 16 + c2;
    float4 v0 = __ldg(p), v1 = __ldg(p + 1);
    a0.x += v0.x; a0.y += v0.y; a0.z += v0.z; a0.w += v0.w;
    a1.x += v1.x; a1.y += v1.y; a1.z += v1.z; a1.w += v1.w;
}

__global__ void aggregate1_kernel() {
    int tid = blockIdx.x * blockDim.x + threadIdx.x;
    int n = tid >> 3;
    if (n >= N_NODES) return;
    int c2 = (tid & 7) << 1;
    int i   = __ldg(&g_off[n]);
    int end = i + __ldg(&g_deg_in[n]);
    const float4* hs4 = reinterpret_cast<const float4*>(g_hs);
    float4 a0 = make_float4(0.f,0.f,0.f,0.f);
    float4 a1 = a0;
    while ((i & 3) && i < end) acc_row(hs4, __ldg(&g_esrc[i++]), c2, a0, a1);
    const int4* e4 = reinterpret_cast<const int4*>(g_esrc);
    for (; i + 4 <= end; i += 4) {
        int4 q = __ldg(&e4[i >> 2]);
        acc_row(hs4, q.x, c2, a0, a1);
        acc_row(hs4, q.y, c2, a0, a1);
        acc_row(hs4, q.z, c2, a0, a1);
        acc_row(hs4, q.w, c2, a0, a1);
    }
    for (; i < end; i++) acc_row(hs4, __ldg(&g_esrc[i]), c2, a0, a1);
    float4* o = reinterpret_cast<float4*>(g_agg1) + (size_t)n * 16 + c2;
    o[0] = a0; o[1] = a1;
}

// Fused persistent GEMM, 1024 threads, grid=148, 128-row tiles.
// Memory behavior identical to R10; inner loops use FFMA2 with register-packed
// A broadcasts (1 MOV feeds 2 FFMA2) and W pairs from natural contiguity.
__global__ __launch_bounds__(1024) void fused_gemm_kernel(const float* __restrict__ W1,
                                                          const float* __restrict__ b1,
                                                          const float* __restrict__ W2) {
    extern __shared__ __align__(16) float sm[];
    float* Ws1 = sm + WS1_OFF;    // [k][128 cols]
    float* Ws2 = sm + WS2_OFF;    // [k][64 cols]
    float* As  = sm + AS_OFF;     // [row 128][k 64] row-major
    float* H1s = sm + H1_OFF;     // [row 128][col 128 pad 132] row-major
    int t = threadIdx.x;

    for (int i = t; i < F_IN * F_MID / 4; i += 1024)
        reinterpret_cast<float4*>(Ws1)[i] = __ldg(reinterpret_cast<const float4*>(W1) + i);
    for (int i = t; i < F_MID * F_IN / 4; i += 1024)
        reinterpret_cast<float4*>(Ws2)[i] = __ldg(reinterpret_cast<const float4*>(W2) + i);

    int ct = t & 31;       // phase1 cols 4*ct
    int rt = t >> 5;       // phase1 rows 4*rt
    int ct2 = t & 15;      // phase2 cols 4*ct2
    int rt2 = t >> 4;      // phase2 rows 2*rt2

    float4 bb = __ldg(reinterpret_cast<const float4*>(b1) + ct);

    for (int tile = blockIdx.x; tile < NTILES; tile += gridDim.x) {
        int row0 = tile * GTILE;
        __syncthreads();

        for (int i = t; i < GTILE * F_IN / 4; i += 1024) {
            int r  = i >> 4;
            int c4 = i & 15;
            int row = row0 + r;
            float4 v = (row < N_NODES)
                ? *reinterpret_cast<const float4*>(g_agg1 + (size_t)row * F_IN + (c4 << 2))
                : make_float4(0.f, 0.f, 0.f, 0.f);
            *reinterpret_cast<float4*>(&As[r * F_IN + (c4 << 2)]) = v;
        }
        __syncthreads();

        // ---- phase 1: 4 rows x 4 cols (2 col-pairs) per thread, FFMA2 ----
        u64 acc[4][2];
#pragma unroll
        for (int j = 0; j < 4; j++) { acc[j][0] = 0ull; acc[j][1] = 0ull; }

        int rbase = rt << 2;
#pragma unroll 4
        for (int k4 = 0; k4 < F_IN / 4; k4++) {
            float4 a0 = *reinterpret_cast<const float4*>(&As[(rbase + 0) * F_IN + (k4 << 2)]);
            float4 a1 = *reinterpret_cast<const float4*>(&As[(rbase + 1) * F_IN + (k4 << 2)]);
            float4 a2 = *reinterpret_cast<const float4*>(&As[(rbase + 2) * F_IN + (k4 << 2)]);
            float4 a3 = *reinterpret_cast<const float4*>(&As[(rbase + 3) * F_IN + (k4 << 2)]);
#pragma unroll
            for (int kk = 0; kk < 4; kk++) {
                ulonglong2 w = *reinterpret_cast<const ulonglong2*>(
                    &Ws1[((k4 << 2) + kk) * F_MID + (ct << 2)]);
                float av0 = kk == 0 ? a0.x : kk == 1 ? a0.y : kk == 2 ? a0.z : a0.w;
                float av1 = kk == 0 ? a1.x : kk == 1 ? a1.y : kk == 2 ? a1.z : a1.w;
                float av2 = kk == 0 ? a2.x : kk == 1 ? a2.y : kk == 2 ? a2.z : a2.w;
                float av3 = kk == 0 ? a3.x : kk == 1 ? a3.y : kk == 2 ? a3.z : a3.w;
                u64 p0 = pack_dup(av0), p1 = pack_dup(av1);
                u64 p2 = pack_dup(av2), p3 = pack_dup(av3);
                fma2(acc[0][0], p0, w.x); fma2(acc[0][1], p0, w.y);
                fma2(acc[1][0], p1, w.x); fma2(acc[1][1], p1, w.y);
                fma2(acc[2][0], p2, w.x); fma2(acc[2][1], p2, w.y);
                fma2(acc[3][0], p3, w.x); fma2(acc[3][1], p3, w.y);
            }
        }
#pragma unroll
        for (int j = 0; j < 4; j++) {
            int lr = rbase + j;
            int row = row0 + lr;
            float nd = (row < N_NODES) ? __ldg(&g_norm_dst[row]) : 0.f;
            float2 u0 = unpack2(acc[j][0]);
            float2 u1 = unpack2(acc[j][1]);
            float4 o;
            o.x = fmaxf(fmaf(u0.x, nd, bb.x), 0.f);
            o.y = fmaxf(fmaf(u0.y, nd, bb.y), 0.f);
            o.z = fmaxf(fmaf(u1.x, nd, bb.z), 0.f);
            o.w = fmaxf(fmaf(u1.y, nd, bb.w), 0.f);
            *reinterpret_cast<float4*>(&H1s[lr * 132 + (ct << 2)]) = o;
        }
        __syncthreads();

        // ---- phase 2: 2 rows x 4 cols (2 col-pairs) per thread, FFMA2 ----
        u64 acc2[2][2];
        acc2[0][0] = acc2[0][1] = acc2[1][0] = acc2[1][1] = 0ull;

        int r0 = rt2 << 1;
#pragma unroll 4
        for (int k4 = 0; k4 < F_MID / 4; k4++) {
            float4 a0v = *reinterpret_cast<const float4*>(&H1s[r0 * 132 + (k4 << 2)]);
            float4 a1v = *reinterpret_cast<const float4*>(&H1s[(r0 + 1) * 132 + (k4 << 2)]);
#pragma unroll
            for (int kk = 0; kk < 4; kk++) {
                ulonglong2 w = *reinterpret_cast<const ulonglong2*>(
                    &Ws2[((k4 << 2) + kk) * F_IN + (ct2 << 2)]);
                float av0 = kk == 0 ? a0v.x : kk == 1 ? a0v.y : kk == 2 ? a0v.z : a0v.w;
                float av1 = kk == 0 ? a1v.x : kk == 1 ? a1v.y : kk == 2 ? a1v.z : a1v.w;
                u64 p0 = pack_dup(av0), p1 = pack_dup(av1);
                fma2(acc2[0][0], p0, w.x); fma2(acc2[0][1], p0, w.y);
                fma2(acc2[1][0], p1, w.x); fma2(acc2[1][1], p1, w.y);
            }
        }
#pragma unroll
        for (int j = 0; j < 2; j++) {
            int row = row0 + r0 + j;
            if (row < N_NODES) {
                float ns = __ldg(&g_norm_src[row]);
                float2 u0 = unpack2(acc2[j][0]);
                float2 u1 = unpack2(acc2[j][1]);
                float4 o;
                o.x = u0.x * ns; o.y = u0.y * ns;
                o.z = u1.x * ns; o.w = u1.y * ns;
                *reinterpret_cast<float4*>(g_t2 + (size_t)row * F_IN + (ct2 << 2)) = o;
            }
        }
    }
}

__global__ void aggregate2_kernel(const float* __restrict__ b2,
                                  float* __restrict__ out) {
    int tid = blockIdx.x * blockDim.x + threadIdx.x;
    int n = tid >> 3;
    if (n >= N_NODES) return;
    int c2 = (tid & 7) << 1;
    int i   = __ldg(&g_off[n]);
    int end = i + __ldg(&g_deg_in[n]);
    const float4* t4 = reinterpret_cast<const float4*>(g_t2);
    float4 a0 = make_float4(0.f,0.f,0.f,0.f);
    float4 a1 = a0;
    while ((i & 3) && i < end) acc_row(t4, __ldg(&g_esrc[i++]), c2, a0, a1);
    const int4* e4 = reinterpret_cast<const int4*>(g_esrc);
    for (; i + 4 <= end; i += 4) {
        int4 q = __ldg(&e4[i >> 2]);
        acc_row(t4, q.x, c2, a0, a1);
        acc_row(t4, q.y, c2, a0, a1);
        acc_row(t4, q.z, c2, a0, a1);
        acc_row(t4, q.w, c2, a0, a1);
    }
    for (; i < end; i++) acc_row(t4, __ldg(&g_esrc[i]), c2, a0, a1);

    float nd = g_norm_dst[n];
    float4 b0 = reinterpret_cast<const float4*>(b2)[c2];
    float4 b1v = reinterpret_cast<const float4*>(b2)[c2 + 1];
    float4 o0, o1;
    o0.x = fmaf(a0.x, nd, b0.x);  o0.y = fmaf(a0.y, nd, b0.y);
    o0.z = fmaf(a0.z, nd, b0.z);  o0.w = fmaf(a0.w, nd, b0.w);
    o1.x = fmaf(a1.x, nd, b1v.x); o1.y = fmaf(a1.y, nd, b1v.y);
    o1.z = fmaf(a1.z, nd, b1v.z); o1.w = fmaf(a1.w, nd, b1v.w);
    float4* o = reinterpret_cast<float4*>(out) + (size_t)n * 16 + c2;
    o[0] = o0; o[1] = o1;
}

// ---------------- launch ----------------
extern "C" void kernel_launch(void* const* d_in, const int* in_sizes, int n_in,
                              void* d_out, int out_size) {
    const float* h   = (const float*)d_in[0];
    const int*   src = (const int*)  d_in[1];
    const int*   dst = (const int*)  d_in[2];
    const float* W1  = (const float*)d_in[3];
    const float* b1  = (const float*)d_in[4];
    const float* W2  = (const float*)d_in[5];
    const float* b2  = (const float*)d_in[6];
    float* out = (float*)d_out;

    cudaFuncSetAttribute(fused_gemm_kernel,
                         cudaFuncAttributeMaxDynamicSharedMemorySize, SMEM_BYTES);

    zero_kernel<<<(N_NODES + 255) / 256, 256>>>();
    degree_kernel<<<(N_EDGES / 2 + 255) / 256, 256>>>(src, dst);
    norm_offset_prescale_kernel<<<(N_NODES + 255) / 256, 256>>>(h);
    fill_kernel<<<(N_EDGES / 2 + 255) / 256, 256>>>(src, dst);

    const int a_threads = N_NODES * 8;
    aggregate1_kernel<<<(a_threads + 255) / 256, 256>>>();

    fused_gemm_kernel<<<148, 1024, SMEM_BYTES>>>(W1, b1, W2);

    aggregate2_kernel<<<(a_threads + 255) / 256, 256>>>(b2, out);
}